// round 9
// baseline (speedup 1.0000x reference)
#include <cuda_runtime.h>
#include <math.h>

#define M_PTS    2048
#define N_VOX    65536
#define NPGRID   10                      // point grid: 10^3 cells, pitch 0.5, [-2.5,2.5)^3 (q-space)
#define NPCELL   (NPGRID*NPGRID*NPGRID)  // 1000
#define NVB      9                       // voxel base-cell grid: 9^3 = 729 (indices 0..8 guaranteed)
#define NVCELL   (NVB*NVB*NVB)           // 729
#define VHB      32                      // histogram/scatter blocks

__device__ float4 g_sorted[M_PTS];           // points grouped by point-cell (q-space)
__device__ int    g_pcellstart[NPCELL + 1];
__device__ int    g_vpart[VHB * NVCELL];     // per-block voxel histograms
__device__ int    g_vstart[NVCELL + 1];
__device__ int    g_vcur[NVCELL];
__device__ float4 g_vpack[N_VOX];            // voxels sorted by base cell: {ux,uy,uz, bits(idx)}
__device__ float4 g_part[NVCELL];            // per-cell partial sums
__device__ unsigned int g_done = 0;          // self-resetting

__device__ __forceinline__ int vox_base_cell(float cx, float cy, float cz) {
    // u = 2*c (q-space); base index = floor(2*u + 4.5) = floor(4*c + 4.5), in [0,8]
    int ix0 = (int)floorf(4.0f * cx + 4.5f);
    int iy0 = (int)floorf(4.0f * cy + 4.5f);
    int iz0 = (int)floorf(4.0f * cz + 4.5f);
    return (ix0 * NVB + iy0) * NVB + iz0;
}

// ---------------- K1: block 0 = matrix + point grid; blocks 1..32 = voxel histograms ----
__global__ __launch_bounds__(1024) void k1_build(
    const float* __restrict__ quat,  const float* __restrict__ tran,
    const float* __restrict__ model, const float* __restrict__ view,
    const float* __restrict__ centers) {
    const int t = threadIdx.x;

    if (blockIdx.x != 0) {
        // ---- voxel histogram (private per block, no global reset needed) ----
        __shared__ int h[NVCELL];
        for (int i = t; i < NVCELL; i += 1024) h[i] = 0;
        __syncthreads();
        const int base = (blockIdx.x - 1) * 2048;
#pragma unroll
        for (int k = 0; k < 2; k++) {
            int v = base + k * 1024 + t;
            float cx = centers[3 * v + 0], cy = centers[3 * v + 1], cz = centers[3 * v + 2];
            atomicAdd(&h[vox_base_cell(cx, cy, cz)], 1);
        }
        __syncthreads();
        int* row = &g_vpart[(blockIdx.x - 1) * NVCELL];
        for (int i = t; i < NVCELL; i += 1024) row[i] = h[i];
        return;
    }

    // ---- block 0: matrix, transform, point-grid counting sort ----
    __shared__ float Ms[16];
    __shared__ float px[M_PTS], py[M_PTS], pz[M_PTS];
    __shared__ short cellof[M_PTS];
    __shared__ int   cnt[1024];
    __shared__ int   cur[NPCELL];
    __shared__ int   wsum[32], wscan[32];

    cnt[t] = 0;
    const int lane = t & 31, w = t >> 5;

    if (t == 0) {
        float q[4]; float s = 0.0f;
#pragma unroll
        for (int i = 0; i < 4; i++) { q[i] = quat[i]; s += q[i] * q[i]; }
        float f = sqrtf(2.0f / s);
#pragma unroll
        for (int i = 0; i < 4; i++) q[i] *= f;
        float Q[4][4];
#pragma unroll
        for (int i = 0; i < 4; i++)
#pragma unroll
            for (int j = 0; j < 4; j++) Q[i][j] = q[i] * q[j];
        float E[4][4] = {
            {1.0f - Q[2][2] - Q[3][3], Q[1][2] - Q[3][0],        Q[1][3] + Q[2][0],        tran[0]},
            {Q[1][2] + Q[3][0],        1.0f - Q[1][1] - Q[3][3], Q[2][3] - Q[1][0],        tran[1]},
            {Q[1][3] - Q[2][0],        Q[2][3] + Q[1][0],        1.0f - Q[1][1] - Q[2][2], tran[2]},
            {0.0f, 0.0f, 0.0f, 1.0f}};
        float A[4][8];
        for (int i = 0; i < 4; i++)
            for (int j = 0; j < 4; j++) {
                A[i][j]     = view[i * 4 + j];
                A[i][j + 4] = (i == j) ? 1.0f : 0.0f;
            }
        for (int col = 0; col < 4; col++) {
            int piv = col; float best = fabsf(A[col][col]);
            for (int r = col + 1; r < 4; r++)
                if (fabsf(A[r][col]) > best) { best = fabsf(A[r][col]); piv = r; }
            if (piv != col)
                for (int j = 0; j < 8; j++) { float tmp = A[col][j]; A[col][j] = A[piv][j]; A[piv][j] = tmp; }
            float d = 1.0f / A[col][col];
            for (int j = 0; j < 8; j++) A[col][j] *= d;
            for (int r = 0; r < 4; r++) {
                if (r == col) continue;
                float m = A[r][col];
                for (int j = 0; j < 8; j++) A[r][j] -= m * A[col][j];
            }
        }
        for (int i = 0; i < 4; i++)
            for (int j = 0; j < 4; j++) {
                float acc = 0.0f;
                for (int k = 0; k < 4; k++) acc += A[i][k + 4] * E[k][j];
                Ms[i * 4 + j] = acc;
            }
    }
    __syncthreads();

    for (int i = t; i < M_PTS; i += 1024) {
        float mx = model[3 * i + 0], my = model[3 * i + 1], mz = model[3 * i + 2];
        float hx = Ms[0]  * mx + Ms[1]  * my + Ms[2]  * mz + Ms[3];
        float hy = Ms[4]  * mx + Ms[5]  * my + Ms[6]  * mz + Ms[7];
        float hz = Ms[8]  * mx + Ms[9]  * my + Ms[10] * mz + Ms[11];
        float hw = Ms[12] * mx + Ms[13] * my + Ms[14] * mz + Ms[15];
        float inv = 2.0f / hw;               // pred / RES
        float x = hx * inv, y = hy * inv, z = hz * inv;
        px[i] = x; py[i] = y; pz[i] = z;
        int ix = (int)floorf(2.0f * x + 5.0f);
        int iy = (int)floorf(2.0f * y + 5.0f);
        int iz = (int)floorf(2.0f * z + 5.0f);
        short cell = -1;
        // Points outside [-2.5,2.5)^3 are >= 0.25 from every center (centers in
        // [-2,2)^3 in q-space) -> the RES/2 clamp makes them irrelevant: discard.
        if (ix >= 0 && ix < NPGRID && iy >= 0 && iy < NPGRID && iz >= 0 && iz < NPGRID) {
            cell = (short)((ix * NPGRID + iy) * NPGRID + iz);
            atomicAdd(&cnt[cell], 1);
        }
        cellof[i] = cell;
    }
    __syncthreads();

    // exclusive scan of cnt[0..1023] (1 value/thread)
    int c = cnt[t];
    int incl = c;
#pragma unroll
    for (int off = 1; off < 32; off <<= 1) {
        int v = __shfl_up_sync(0xffffffffu, incl, off);
        if (lane >= off) incl += v;
    }
    if (lane == 31) wsum[w] = incl;
    __syncthreads();
    if (t < 32) {
        int v = wsum[t];
#pragma unroll
        for (int off = 1; off < 32; off <<= 1) {
            int u = __shfl_up_sync(0xffffffffu, v, off);
            if (t >= off) v += u;
        }
        wscan[t] = v;
    }
    __syncthreads();
    int excl = ((w > 0) ? wscan[w - 1] : 0) + incl - c;
    if (t < NPCELL) {
        g_pcellstart[t] = excl;
        cur[t] = excl;
    }
    if (t == NPCELL - 1) g_pcellstart[NPCELL] = excl + c;
    __syncthreads();

    for (int i = t; i < M_PTS; i += 1024) {
        int cell = cellof[i];
        if (cell >= 0) {
            int pos = atomicAdd(&cur[cell], 1);
            g_sorted[pos] = make_float4(px[i], py[i], pz[i], 0.0f);
        }
    }
}

// ---------------- K2: reduce partials + scan voxel bins (1 block) ----------------
__global__ __launch_bounds__(1024) void k2_scan() {
    __shared__ int wsum[32], wscan[32];
    const int t = threadIdx.x;
    const int lane = t & 31, w = t >> 5;
    int c = 0;
    if (t < NVCELL) {
#pragma unroll
        for (int b = 0; b < VHB; b++) c += g_vpart[b * NVCELL + t];
    }
    int incl = c;
#pragma unroll
    for (int off = 1; off < 32; off <<= 1) {
        int v = __shfl_up_sync(0xffffffffu, incl, off);
        if (lane >= off) incl += v;
    }
    if (lane == 31) wsum[w] = incl;
    __syncthreads();
    if (t < 32) {
        int v = wsum[t];
#pragma unroll
        for (int off = 1; off < 32; off <<= 1) {
            int u = __shfl_up_sync(0xffffffffu, v, off);
            if (t >= off) v += u;
        }
        wscan[t] = v;
    }
    __syncthreads();
    int excl = ((w > 0) ? wscan[w - 1] : 0) + incl - c;
    if (t < NVCELL) {
        g_vstart[t] = excl;
        g_vcur[t]   = excl;
    }
    if (t == NVCELL - 1) g_vstart[NVCELL] = excl + c;
}

// ---------------- K3: scatter voxels sorted by base cell ----------------
__global__ __launch_bounds__(1024) void k3_scatter(const float* __restrict__ centers) {
    const int t = threadIdx.x;
    const int base = blockIdx.x * 2048;
#pragma unroll
    for (int k = 0; k < 2; k++) {
        int v = base + k * 1024 + t;
        float cx = centers[3 * v + 0], cy = centers[3 * v + 1], cz = centers[3 * v + 2];
        int b = vox_base_cell(cx, cy, cz);
        int pos = atomicAdd(&g_vcur[b], 1);
        g_vpack[pos] = make_float4(2.0f * cx, 2.0f * cy, 2.0f * cz, __int_as_float(v));
    }
}

// ---------------- K4: one block per voxel cell, uniform point loops, full reduction ----
__global__ __launch_bounds__(128) void k4_query(
    const float* __restrict__ freev, const float* __restrict__ occo,
    const float* __restrict__ masks, float* __restrict__ out) {
    __shared__ float red[4][4];
    __shared__ bool  amLast;

    const int t = threadIdx.x;
    const int lane = t & 31, w = t >> 5;
    const int B = blockIdx.x;
    const int ix0 = B / (NVB * NVB);
    const int rem = B % (NVB * NVB);
    const int iy0 = rem / NVB;
    const int iz0 = rem % NVB;

    // 4 contiguous point runs (z-pair cells iz0, iz0+1 are adjacent in the point grid)
    int rs[4], re[4];
#pragma unroll
    for (int a = 0; a < 2; a++)
#pragma unroll
        for (int b = 0; b < 2; b++) {
            int cb = ((ix0 + a) * NPGRID + (iy0 + b)) * NPGRID + iz0;
            rs[a * 2 + b] = g_pcellstart[cb];
            re[a * 2 + b] = g_pcellstart[cb + 2];
        }

    const int vs = g_vstart[B], ve = g_vstart[B + 1];
    float aps = 0.f, as1 = 0.f, as2 = 0.f, ams = 0.f;

    for (int basei = vs; basei < ve; basei += 128) {
        int i = basei + t;
        bool act = (i < ve);
        float4 vp = act ? g_vpack[i] : make_float4(0.f, 0.f, 0.f, 0.f);
        float ux = vp.x, uy = vp.y, uz = vp.z;

        float m = 1e30f;
#pragma unroll
        for (int r = 0; r < 4; r++) {
            for (int k = rs[r]; k < re[r]; k++) {    // uniform bounds, broadcast loads
                float4 p = g_sorted[k];
                float dx = ux - p.x, dy = uy - p.y, dz = uz - p.z;
                float d2 = fmaf(dx, dx, fmaf(dy, dy, dz * dz));
                m = fminf(m, d2);
            }
        }

        float fo = 0.f, mk = 0.f;
        if (act) {
            int v = __float_as_int(vp.w);
            fo = freev[v] + occo[v];
            mk = masks[v];
        }
        float d = sqrtf(fmaxf(m, 0.0f));
        d = fminf(d, 0.25f);
        float o = fmaxf(1.0f - 4.0f * d, 0.0f);
        if (!act) o = 0.f;
        aps += o; as1 += fo * o; as2 += mk * o; ams += mk;
    }

    const unsigned full = 0xffffffffu;
#pragma unroll
    for (int off = 16; off > 0; off >>= 1) {
        aps += __shfl_down_sync(full, aps, off);
        as1 += __shfl_down_sync(full, as1, off);
        as2 += __shfl_down_sync(full, as2, off);
        ams += __shfl_down_sync(full, ams, off);
    }
    if (lane == 0) { red[0][w] = aps; red[1][w] = as1; red[2][w] = as2; red[3][w] = ams; }
    __syncthreads();
    if (t == 0) {
        float tps = 0.f, ts1 = 0.f, ts2 = 0.f, tms = 0.f;
#pragma unroll
        for (int i = 0; i < 4; i++) {
            tps += red[0][i]; ts1 += red[1][i]; ts2 += red[2][i]; tms += red[3][i];
        }
        g_part[B] = make_float4(tps, ts1, ts2, tms);
        __threadfence();
        unsigned r = atomicAdd(&g_done, 1u);
        amLast = (r == NVCELL - 1);
    }
    __syncthreads();

    if (amLast) {
        float4 acc = make_float4(0.f, 0.f, 0.f, 0.f);
        for (int i = t; i < NVCELL; i += 128) {
            float4 p = __ldcg(&g_part[i]);
            acc.x += p.x; acc.y += p.y; acc.z += p.z; acc.w += p.w;
        }
#pragma unroll
        for (int off = 16; off > 0; off >>= 1) {
            acc.x += __shfl_down_sync(full, acc.x, off);
            acc.y += __shfl_down_sync(full, acc.y, off);
            acc.z += __shfl_down_sync(full, acc.z, off);
            acc.w += __shfl_down_sync(full, acc.w, off);
        }
        if (lane == 0) { red[0][w] = acc.x; red[1][w] = acc.y; red[2][w] = acc.z; red[3][w] = acc.w; }
        __syncthreads();
        if (t == 0) {
            double ps = 0.0, s1 = 0.0, s2 = 0.0, ms = 0.0;
#pragma unroll
            for (int i = 0; i < 4; i++) {
                ps += (double)red[0][i]; s1 += (double)red[1][i];
                s2 += (double)red[2][i]; ms += (double)red[3][i];
            }
            double t1 = (ps > 0.0) ? s1 / ps : 0.0;
            double t2 = (ms > 0.0) ? s2 / ms : 0.0;
            out[0] = (float)(t1 - t2);
            g_done = 0;   // reset for next graph replay
        }
    }
}

extern "C" void kernel_launch(void* const* d_in, const int* in_sizes, int n_in,
                              void* d_out, int out_size) {
    const float* quat    = (const float*)d_in[0];
    const float* tran    = (const float*)d_in[1];
    const float* model   = (const float*)d_in[2];
    const float* view    = (const float*)d_in[3];
    const float* centers = (const float*)d_in[4];
    const float* freev   = (const float*)d_in[5];
    const float* occo    = (const float*)d_in[6];
    const float* masks   = (const float*)d_in[7];
    (void)in_sizes; (void)n_in; (void)out_size;

    k1_build<<<1 + VHB, 1024>>>(quat, tran, model, view, centers);
    k2_scan<<<1, 1024>>>();
    k3_scatter<<<VHB, 1024>>>(centers);
    k4_query<<<NVCELL, 128>>>(freev, occo, masks, (float*)d_out);
}